// round 11
// baseline (speedup 1.0000x reference)
#include <cuda_runtime.h>

#define BATCH 16
#define TLEN  512
#define DIMSZ 384
#define DMAX  4096
#define MAIN  (BATCH * DIMSZ * DMAX)   // 25,165,824 floats
#define ROWS  4                        // d-rows per block

// ---------------------------------------------------------------------------
// Fused kernel: grid (96, 16) = 1536 blocks x 256 threads (R5 shape, best
// measured). Store policy experiment R11: __stwt write-through. Stores go
// straight to DRAM in program order (sequential within each 16KB output row
// -> row-buffer friendly) and leave no dirty L2 state, removing the
// hash-ordered writeback drain that has pinned wall time at ~21us.
// ---------------------------------------------------------------------------
__global__ void __launch_bounds__(256, 8) length_regulator_kernel(
    const float* __restrict__ x, const int* __restrict__ dur,
    float* __restrict__ out, int out_size)
{
    const int b   = blockIdx.y;
    const int dg  = blockIdx.x;          // 0..95
    const int tid = threadIdx.x;         // 0..255
    const int d0  = dg * ROWS;

    __shared__ short s_idx[DMAX];        // 8 KB (indices < 512 fit in int16)
    __shared__ float s_x[ROWS * TLEN];   // 8 KB
    __shared__ int   wsum[8], woff[8];

    // ---- stage x rows (512 float4, 2/thread, coalesced) ----
    const float4* xb4 = reinterpret_cast<const float4*>(
        x + ((size_t)b * DIMSZ + d0) * TLEN);
    reinterpret_cast<float4*>(s_x)[tid]       = xb4[tid];
    reinterpret_cast<float4*>(s_x)[tid + 256] = xb4[tid + 256];

    // ---- init idx to -1 (0xFFFF shorts via int4 writes: 512 int4, 2/thread)
    {
        const int4 m1 = make_int4(-1, -1, -1, -1);
        reinterpret_cast<int4*>(s_idx)[tid]       = m1;
        reinterpret_cast<int4*>(s_idx)[tid + 256] = m1;
    }

    // ---- scan 512 durations with 256 threads (2 adjacent steps/thread) ----
    const int2 dd = reinterpret_cast<const int2*>(dur + b * TLEN)[tid];
    int da = dd.x, db = dd.y;
    const int lane = tid & 31;
    const int wid  = tid >> 5;           // 0..7

    int v = da + db;                     // pair sum
    const int pair = v;
    #pragma unroll
    for (int o = 1; o < 32; o <<= 1) {
        int n = __shfl_up_sync(0xffffffffu, v, o);
        if (lane >= o) v += n;
    }
    if (lane == 31) wsum[wid] = v;
    __syncthreads();
    if (tid < 8) {
        int w = wsum[tid];
        #pragma unroll
        for (int o = 1; o < 8; o <<= 1) {
            int n = __shfl_up_sync(0x000000ffu, w, o);
            if (tid >= o) w += n;
        }
        woff[tid] = w;
    }
    __syncthreads();

    const int total = woff[7];
    int c0, c1, mel;
    if (total == 0) {                    // all-zero row: duration := 1
        da = 1; db = 1;
        c0 = 2 * tid + 1;
        c1 = 2 * tid + 2;
        mel = TLEN;
    } else {
        const int excl = v - pair + (wid ? woff[wid - 1] : 0);
        c0 = excl + da;
        c1 = c0 + db;
        mel = total;
    }

    // ---- scatter timestep ids into smem idx (disjoint ranges) ----
    {
        const short t0 = (short)(2 * tid), t1 = (short)(2 * tid + 1);
        int s0 = c0 - da;
        for (int k = 0; k < da; k++) s_idx[s0 + k] = t0;
        int s1 = c1 - db;
        for (int k = 0; k < db; k++) s_idx[s1 + k] = t1;
    }
    __syncthreads();

    // ---- gather + write-through stores ----
    float* ob = out + ((size_t)b * DIMSZ + d0) * DMAX;

    #pragma unroll
    for (int s = 0; s < 4; s++) {
        const int slot = s * 256 + tid;              // float4 slot 0..1023
        const short4 iv = reinterpret_cast<const short4*>(s_idx)[slot];
        const int i0 = iv.x, i1 = iv.y, i2 = iv.z, i3 = iv.w;
        #pragma unroll
        for (int r = 0; r < ROWS; r++) {
            const float* sx = s_x + r * TLEN;
            float4 val;
            val.x = (i0 >= 0) ? sx[i0] : 0.0f;
            val.y = (i1 >= 0) ? sx[i1] : 0.0f;
            val.z = (i2 >= 0) ? sx[i2] : 0.0f;
            val.w = (i3 >= 0) ? sx[i3] : 0.0f;
            __stwt(reinterpret_cast<float4*>(ob + (size_t)r * DMAX) + slot, val);
        }
    }

    // ---- mel_len output + tail zeroing ----
    if (dg == 0) {
        if (tid == 0 && out_size >= MAIN + BATCH)
            out[MAIN + b] = (float)mel;
        if (b == 0) {
            for (int p = MAIN + BATCH + tid; p < out_size; p += 256)
                out[p] = 0.0f;
        }
    }
}

extern "C" void kernel_launch(void* const* d_in, const int* in_sizes, int n_in,
                              void* d_out, int out_size)
{
    const float* x   = (const float*)d_in[0];   // (16, 384, 512) f32
    const int*   dur = (const int*)d_in[1];     // (16, 512) i32
    float*       out = (float*)d_out;

    length_regulator_kernel<<<dim3(DIMSZ / ROWS, BATCH), 256>>>(x, dur, out, out_size);
}

// round 12
// speedup vs baseline: 1.1045x; 1.1045x over previous
#include <cuda_runtime.h>

#define BATCH 16
#define TLEN  512
#define DIMSZ 384
#define DMAX  4096
#define MAIN  (BATCH * DIMSZ * DMAX)   // 25,165,824 floats
#define ROWS  4                        // d-rows per block
#define MAXMEL 3584                    // duration < 8 -> mel <= 7*512 = 3584
#define GSLOTS (MAXMEL / 4)            // 896 gather float4 slots per row

// ---------------------------------------------------------------------------
// Fused kernel: grid (96, 16) = 1536 blocks x 256 threads, stcs stores
// (best measured policy). R12 changes:
//  * Frames [3584, 4096) are provably always padding (dur<8) -> their zero
//    stores issue at kernel entry, overlapping the scan/scatter prologue.
//  * s_idx is never initialized: pad is a per-element (frame < mel) select
//    with &511 masking, removing the init memset from the critical path and
//    shrinking gather work by 12.5%.
// ---------------------------------------------------------------------------
__global__ void __launch_bounds__(256, 8) length_regulator_kernel(
    const float* __restrict__ x, const int* __restrict__ dur,
    float* __restrict__ out, int out_size)
{
    const int b   = blockIdx.y;
    const int dg  = blockIdx.x;          // 0..95
    const int tid = threadIdx.x;         // 0..255
    const int d0  = dg * ROWS;

    __shared__ short s_idx[MAXMEL];      // 7 KB, NOT initialized (masked reads)
    __shared__ float s_x[ROWS * TLEN];   // 8 KB
    __shared__ int   wsum[8], woff[8];

    float* ob = out + ((size_t)b * DIMSZ + d0) * DMAX;

    // ---- phase 0: unconditional-pad zero stores, issued before anything ----
    {
        const float4 z = make_float4(0.f, 0.f, 0.f, 0.f);
        const int zslot = GSLOTS + (tid & 127);       // 896..1023
        const int rbase = tid >> 7;                   // 0 or 1
        __stcs(reinterpret_cast<float4*>(ob + (size_t)rbase * DMAX) + zslot, z);
        __stcs(reinterpret_cast<float4*>(ob + (size_t)(rbase + 2) * DMAX) + zslot, z);
    }

    // ---- stage x rows (512 float4, 2/thread, coalesced) ----
    const float4* xb4 = reinterpret_cast<const float4*>(
        x + ((size_t)b * DIMSZ + d0) * TLEN);
    reinterpret_cast<float4*>(s_x)[tid]       = xb4[tid];
    reinterpret_cast<float4*>(s_x)[tid + 256] = xb4[tid + 256];

    // ---- scan 512 durations with 256 threads (2 adjacent steps/thread) ----
    const int2 dd = reinterpret_cast<const int2*>(dur + b * TLEN)[tid];
    int da = dd.x, db = dd.y;
    const int lane = tid & 31;
    const int wid  = tid >> 5;           // 0..7

    int v = da + db;                     // pair sum
    const int pair = v;
    #pragma unroll
    for (int o = 1; o < 32; o <<= 1) {
        int n = __shfl_up_sync(0xffffffffu, v, o);
        if (lane >= o) v += n;
    }
    if (lane == 31) wsum[wid] = v;
    __syncthreads();
    if (tid < 8) {
        int w = wsum[tid];
        #pragma unroll
        for (int o = 1; o < 8; o <<= 1) {
            int n = __shfl_up_sync(0x000000ffu, w, o);
            if (tid >= o) w += n;
        }
        woff[tid] = w;
    }
    __syncthreads();

    const int total = woff[7];
    int c0, c1, mel;
    if (total == 0) {                    // all-zero row: duration := 1
        da = 1; db = 1;
        c0 = 2 * tid + 1;
        c1 = 2 * tid + 2;
        mel = TLEN;
    } else {
        const int excl = v - pair + (wid ? woff[wid - 1] : 0);
        c0 = excl + da;
        c1 = c0 + db;
        mel = total;
    }

    // ---- scatter timestep ids into smem idx (disjoint ranges, cover [0,mel))
    {
        const short t0 = (short)(2 * tid), t1 = (short)(2 * tid + 1);
        int s0 = c0 - da;
        for (int k = 0; k < da; k++) s_idx[s0 + k] = t0;
        int s1 = c1 - db;
        for (int k = 0; k < db; k++) s_idx[s1 + k] = t1;
    }
    __syncthreads();

    // ---- gather + streaming stores over frames [0, 3584) ----
    #pragma unroll
    for (int s = 0; s < 4; s++) {
        const int slot = s * 256 + tid;              // float4 slot
        if (slot < GSLOTS) {                         // warp-uniform guard
            const int fbase = slot * 4;
            const short4 iv = reinterpret_cast<const short4*>(s_idx)[slot];
            const int i0 = iv.x & 511, i1 = iv.y & 511;
            const int i2 = iv.z & 511, i3 = iv.w & 511;
            const bool v0 = fbase     < mel, v1 = fbase + 1 < mel;
            const bool v2 = fbase + 2 < mel, v3 = fbase + 3 < mel;
            #pragma unroll
            for (int r = 0; r < ROWS; r++) {
                const float* sx = s_x + r * TLEN;
                float4 val;
                val.x = v0 ? sx[i0] : 0.0f;
                val.y = v1 ? sx[i1] : 0.0f;
                val.z = v2 ? sx[i2] : 0.0f;
                val.w = v3 ? sx[i3] : 0.0f;
                __stcs(reinterpret_cast<float4*>(ob + (size_t)r * DMAX) + slot, val);
            }
        }
    }

    // ---- mel_len output + tail zeroing ----
    if (dg == 0) {
        if (tid == 0 && out_size >= MAIN + BATCH)
            out[MAIN + b] = (float)mel;
        if (b == 0) {
            for (int p = MAIN + BATCH + tid; p < out_size; p += 256)
                out[p] = 0.0f;
        }
    }
}

extern "C" void kernel_launch(void* const* d_in, const int* in_sizes, int n_in,
                              void* d_out, int out_size)
{
    const float* x   = (const float*)d_in[0];   // (16, 384, 512) f32
    const int*   dur = (const int*)d_in[1];     // (16, 512) i32
    float*       out = (float*)d_out;

    length_regulator_kernel<<<dim3(DIMSZ / ROWS, BATCH), 256>>>(x, dur, out, out_size);
}

// round 13
// speedup vs baseline: 1.1182x; 1.0124x over previous
#include <cuda_runtime.h>

#define BATCH 16
#define TLEN  512
#define DIMSZ 384
#define DMAX  4096
#define MAIN  (BATCH * DIMSZ * DMAX)   // 25,165,824 floats
#define ROWS  4                        // d-rows per block
#define MAXMEL 3584                    // duration < 8 -> mel <= 7*512 = 3584
#define GSLOTS (MAXMEL / 4)            // 896 gather float4 slots per row

// ---------------------------------------------------------------------------
// Fused kernel: grid (96, 16) = 1536 blocks x 256 threads, stcs stores.
// R13 = R12 + per-slot pad short-circuit: slots whose 4 frames are all
// >= mel store zeros directly (no idx LDS, no 16 gather LDS). Indices are
// monotonic so the branch is warp-quasi-uniform; this strictly removes
// ~45% of gather-path smem traffic vs R12.
// ---------------------------------------------------------------------------
__global__ void __launch_bounds__(256, 8) length_regulator_kernel(
    const float* __restrict__ x, const int* __restrict__ dur,
    float* __restrict__ out, int out_size)
{
    const int b   = blockIdx.y;
    const int dg  = blockIdx.x;          // 0..95
    const int tid = threadIdx.x;         // 0..255
    const int d0  = dg * ROWS;

    __shared__ short s_idx[MAXMEL];      // 7 KB, NOT initialized (masked reads)
    __shared__ float s_x[ROWS * TLEN];   // 8 KB
    __shared__ int   wsum[8], woff[8];

    float* ob = out + ((size_t)b * DIMSZ + d0) * DMAX;

    // ---- phase 0: unconditional-pad zero stores, issued before anything ----
    {
        const float4 z = make_float4(0.f, 0.f, 0.f, 0.f);
        const int zslot = GSLOTS + (tid & 127);       // 896..1023
        const int rbase = tid >> 7;                   // 0 or 1
        __stcs(reinterpret_cast<float4*>(ob + (size_t)rbase * DMAX) + zslot, z);
        __stcs(reinterpret_cast<float4*>(ob + (size_t)(rbase + 2) * DMAX) + zslot, z);
    }

    // ---- stage x rows (512 float4, 2/thread, coalesced) ----
    const float4* xb4 = reinterpret_cast<const float4*>(
        x + ((size_t)b * DIMSZ + d0) * TLEN);
    reinterpret_cast<float4*>(s_x)[tid]       = xb4[tid];
    reinterpret_cast<float4*>(s_x)[tid + 256] = xb4[tid + 256];

    // ---- scan 512 durations with 256 threads (2 adjacent steps/thread) ----
    const int2 dd = reinterpret_cast<const int2*>(dur + b * TLEN)[tid];
    int da = dd.x, db = dd.y;
    const int lane = tid & 31;
    const int wid  = tid >> 5;           // 0..7

    int v = da + db;                     // pair sum
    const int pair = v;
    #pragma unroll
    for (int o = 1; o < 32; o <<= 1) {
        int n = __shfl_up_sync(0xffffffffu, v, o);
        if (lane >= o) v += n;
    }
    if (lane == 31) wsum[wid] = v;
    __syncthreads();
    if (tid < 8) {
        int w = wsum[tid];
        #pragma unroll
        for (int o = 1; o < 8; o <<= 1) {
            int n = __shfl_up_sync(0x000000ffu, w, o);
            if (tid >= o) w += n;
        }
        woff[tid] = w;
    }
    __syncthreads();

    const int total = woff[7];
    int c0, c1, mel;
    if (total == 0) {                    // all-zero row: duration := 1
        da = 1; db = 1;
        c0 = 2 * tid + 1;
        c1 = 2 * tid + 2;
        mel = TLEN;
    } else {
        const int excl = v - pair + (wid ? woff[wid - 1] : 0);
        c0 = excl + da;
        c1 = c0 + db;
        mel = total;
    }

    // ---- scatter timestep ids into smem idx (disjoint ranges, cover [0,mel))
    {
        const short t0 = (short)(2 * tid), t1 = (short)(2 * tid + 1);
        int s0 = c0 - da;
        for (int k = 0; k < da; k++) s_idx[s0 + k] = t0;
        int s1 = c1 - db;
        for (int k = 0; k < db; k++) s_idx[s1 + k] = t1;
    }
    __syncthreads();

    // ---- gather + streaming stores over frames [0, 3584) ----
    #pragma unroll
    for (int s = 0; s < 4; s++) {
        const int slot = s * 256 + tid;              // float4 slot
        if (slot < GSLOTS) {                         // warp-uniform guard
            const int fbase = slot * 4;
            if (fbase < mel) {
                // at least one valid frame in this quad: gather
                const short4 iv = reinterpret_cast<const short4*>(s_idx)[slot];
                const int i0 = iv.x & 511, i1 = iv.y & 511;
                const int i2 = iv.z & 511, i3 = iv.w & 511;
                const bool v1 = fbase + 1 < mel;
                const bool v2 = fbase + 2 < mel;
                const bool v3 = fbase + 3 < mel;
                #pragma unroll
                for (int r = 0; r < ROWS; r++) {
                    const float* sx = s_x + r * TLEN;
                    float4 val;
                    val.x = sx[i0];
                    val.y = v1 ? sx[i1] : 0.0f;
                    val.z = v2 ? sx[i2] : 0.0f;
                    val.w = v3 ? sx[i3] : 0.0f;
                    __stcs(reinterpret_cast<float4*>(ob + (size_t)r * DMAX) + slot, val);
                }
            } else {
                // whole quad is padding: pure zero stores, no smem traffic
                const float4 z = make_float4(0.f, 0.f, 0.f, 0.f);
                #pragma unroll
                for (int r = 0; r < ROWS; r++)
                    __stcs(reinterpret_cast<float4*>(ob + (size_t)r * DMAX) + slot, z);
            }
        }
    }

    // ---- mel_len output + tail zeroing ----
    if (dg == 0) {
        if (tid == 0 && out_size >= MAIN + BATCH)
            out[MAIN + b] = (float)mel;
        if (b == 0) {
            for (int p = MAIN + BATCH + tid; p < out_size; p += 256)
                out[p] = 0.0f;
        }
    }
}

extern "C" void kernel_launch(void* const* d_in, const int* in_sizes, int n_in,
                              void* d_out, int out_size)
{
    const float* x   = (const float*)d_in[0];   // (16, 384, 512) f32
    const int*   dur = (const int*)d_in[1];     // (16, 512) i32
    float*       out = (float*)d_out;

    length_regulator_kernel<<<dim3(DIMSZ / ROWS, BATCH), 256>>>(x, dur, out, out_size);
}

// round 14
// speedup vs baseline: 1.1199x; 1.0016x over previous
#include <cuda_runtime.h>

#define BATCH 16
#define TLEN  512
#define DIMSZ 384
#define DMAX  4096
#define MAIN  (BATCH * DIMSZ * DMAX)   // 25,165,824 floats
#define ROWS  4                        // d-rows per block
#define MAXMEL 3584                    // duration < 8 -> mel <= 7*512 = 3584
#define GSLOTS (MAXMEL / 4)            // 896 gather float4 slots per row

// ---------------------------------------------------------------------------
// Fused kernel: grid (96, 16) = 1536 blocks x 256 threads, stcs stores.
// R14 = R12 gather structure + WARP-UNIFORM pad short-circuit (no divergence):
//  * frames [3584,4096): unconditional zero stores at kernel entry (phase 0)
//  * warps whose entire 128-frame range is >= mel: pure zero stores
//  * remaining warps: straight-line gather with per-element (frame<mel) select
// ---------------------------------------------------------------------------
__global__ void __launch_bounds__(256, 8) length_regulator_kernel(
    const float* __restrict__ x, const int* __restrict__ dur,
    float* __restrict__ out, int out_size)
{
    const int b   = blockIdx.y;
    const int dg  = blockIdx.x;          // 0..95
    const int tid = threadIdx.x;         // 0..255
    const int d0  = dg * ROWS;

    __shared__ short s_idx[MAXMEL];      // 7 KB, NOT initialized (masked reads)
    __shared__ float s_x[ROWS * TLEN];   // 8 KB
    __shared__ int   wsum[8], woff[8];

    float* ob = out + ((size_t)b * DIMSZ + d0) * DMAX;

    // ---- phase 0: unconditional-pad zero stores, issued before anything ----
    {
        const float4 z = make_float4(0.f, 0.f, 0.f, 0.f);
        const int zslot = GSLOTS + (tid & 127);       // 896..1023
        const int rbase = tid >> 7;                   // 0 or 1
        __stcs(reinterpret_cast<float4*>(ob + (size_t)rbase * DMAX) + zslot, z);
        __stcs(reinterpret_cast<float4*>(ob + (size_t)(rbase + 2) * DMAX) + zslot, z);
    }

    // ---- stage x rows (512 float4, 2/thread, coalesced) ----
    const float4* xb4 = reinterpret_cast<const float4*>(
        x + ((size_t)b * DIMSZ + d0) * TLEN);
    reinterpret_cast<float4*>(s_x)[tid]       = xb4[tid];
    reinterpret_cast<float4*>(s_x)[tid + 256] = xb4[tid + 256];

    // ---- scan 512 durations with 256 threads (2 adjacent steps/thread) ----
    const int2 dd = reinterpret_cast<const int2*>(dur + b * TLEN)[tid];
    int da = dd.x, db = dd.y;
    const int lane = tid & 31;
    const int wid  = tid >> 5;           // 0..7

    int v = da + db;                     // pair sum
    const int pair = v;
    #pragma unroll
    for (int o = 1; o < 32; o <<= 1) {
        int n = __shfl_up_sync(0xffffffffu, v, o);
        if (lane >= o) v += n;
    }
    if (lane == 31) wsum[wid] = v;
    __syncthreads();
    if (tid < 8) {
        int w = wsum[tid];
        #pragma unroll
        for (int o = 1; o < 8; o <<= 1) {
            int n = __shfl_up_sync(0x000000ffu, w, o);
            if (tid >= o) w += n;
        }
        woff[tid] = w;
    }
    __syncthreads();

    const int total = woff[7];
    int c0, c1, mel;
    if (total == 0) {                    // all-zero row: duration := 1
        da = 1; db = 1;
        c0 = 2 * tid + 1;
        c1 = 2 * tid + 2;
        mel = TLEN;
    } else {
        const int excl = v - pair + (wid ? woff[wid - 1] : 0);
        c0 = excl + da;
        c1 = c0 + db;
        mel = total;
    }

    // ---- scatter timestep ids into smem idx (disjoint ranges, cover [0,mel))
    {
        const short t0 = (short)(2 * tid), t1 = (short)(2 * tid + 1);
        int s0 = c0 - da;
        for (int k = 0; k < da; k++) s_idx[s0 + k] = t0;
        int s1 = c1 - db;
        for (int k = 0; k < db; k++) s_idx[s1 + k] = t1;
    }
    __syncthreads();

    // ---- gather + streaming stores over frames [0, 3584) ----
    const int wbase = tid & ~31;         // lane-uniform warp base thread

    #pragma unroll
    for (int s = 0; s < 4; s++) {
        const int slot = s * 256 + tid;              // float4 slot
        if (slot < GSLOTS) {                         // warp-uniform guard
            if ((s * 256 + wbase) * 4 >= mel) {
                // whole warp range is padding: pure zero stores, no smem reads
                const float4 z = make_float4(0.f, 0.f, 0.f, 0.f);
                #pragma unroll
                for (int r = 0; r < ROWS; r++)
                    __stcs(reinterpret_cast<float4*>(ob + (size_t)r * DMAX) + slot, z);
            } else {
                // gather with per-element validity select (no divergence)
                const int fbase = slot * 4;
                const short4 iv = reinterpret_cast<const short4*>(s_idx)[slot];
                const int i0 = iv.x & 511, i1 = iv.y & 511;
                const int i2 = iv.z & 511, i3 = iv.w & 511;
                const bool v0 = fbase     < mel, v1 = fbase + 1 < mel;
                const bool v2 = fbase + 2 < mel, v3 = fbase + 3 < mel;
                #pragma unroll
                for (int r = 0; r < ROWS; r++) {
                    const float* sx = s_x + r * TLEN;
                    float4 val;
                    val.x = v0 ? sx[i0] : 0.0f;
                    val.y = v1 ? sx[i1] : 0.0f;
                    val.z = v2 ? sx[i2] : 0.0f;
                    val.w = v3 ? sx[i3] : 0.0f;
                    __stcs(reinterpret_cast<float4*>(ob + (size_t)r * DMAX) + slot, val);
                }
            }
        }
    }

    // ---- mel_len output + tail zeroing ----
    if (dg == 0) {
        if (tid == 0 && out_size >= MAIN + BATCH)
            out[MAIN + b] = (float)mel;
        if (b == 0) {
            for (int p = MAIN + BATCH + tid; p < out_size; p += 256)
                out[p] = 0.0f;
        }
    }
}

extern "C" void kernel_launch(void* const* d_in, const int* in_sizes, int n_in,
                              void* d_out, int out_size)
{
    const float* x   = (const float*)d_in[0];   // (16, 384, 512) f32
    const int*   dur = (const int*)d_in[1];     // (16, 512) i32
    float*       out = (float*)d_out;

    length_regulator_kernel<<<dim3(DIMSZ / ROWS, BATCH), 256>>>(x, dur, out, out_size);
}